// round 6
// baseline (speedup 1.0000x reference)
#include <cuda_runtime.h>
#include <cuda_bf16.h>
#include <math.h>
#include <stdint.h>

#define NE 8
#define NT 8192
#define NH 768
#define NI 3072
#define BM 128
#define BN 128
#define BK 32
#define THREADS 256
#define MAX_TILES 72
#define NTP (NT + NE*BM)

// per-stage smem layout (bytes). A planes: [128 rows][32 bf16 + 8 pad] = 80B/row.
// B planes: [32 k-rows][128 bf16 + 8 pad] = 272B/row.
#define A_STRIDE 80
#define B_STRIDE 272
#define OFF_AH 0
#define OFF_AL 10240
#define OFF_BH 20480
#define OFF_BL 29184
#define STAGE  37888
#define SMEM_BYTES (2*STAGE)   // 75776

__device__ int g_counts[NE];
__device__ int g_fill[NE];
__device__ int g_offsets[NE+1];
__device__ int g_perm[NTP];
__device__ int g_tile_e[MAX_TILES];
__device__ int g_tile_row0[MAX_TILES];
__device__ int g_ntiles;
__device__ __nv_bfloat16 g_inter_hi[(size_t)NTP*NI];   // 54 MB
__device__ __nv_bfloat16 g_inter_lo[(size_t)NTP*NI];   // 54 MB
__device__ float g_mid[(size_t)NT*NH];                 // 24 MB

static __device__ __forceinline__ uint32_t s2u(const void* p){
    uint32_t a; asm("{ .reg .u64 t; cvta.to.shared.u64 t, %1; cvt.u32.u64 %0, t; }":"=r"(a):"l"(p)); return a;
}
static __device__ __forceinline__ void sts128(uint32_t a, uint32_t x, uint32_t y, uint32_t z, uint32_t w){
    asm volatile("st.shared.v4.b32 [%0], {%1,%2,%3,%4};"::"r"(a),"r"(x),"r"(y),"r"(z),"r"(w):"memory");
}
static __device__ __forceinline__ void ldsm4(uint32_t* r, uint32_t addr){
    asm volatile("ldmatrix.sync.aligned.m8n8.x4.shared.b16 {%0,%1,%2,%3}, [%4];"
        : "=r"(r[0]),"=r"(r[1]),"=r"(r[2]),"=r"(r[3]) : "r"(addr));
}
static __device__ __forceinline__ void ldsm4t(uint32_t* r, uint32_t addr){
    asm volatile("ldmatrix.sync.aligned.m8n8.x4.trans.shared.b16 {%0,%1,%2,%3}, [%4];"
        : "=r"(r[0]),"=r"(r[1]),"=r"(r[2]),"=r"(r[3]) : "r"(addr));
}
static __device__ __forceinline__ void mma16(float* d, const uint32_t* a, uint32_t b0, uint32_t b1){
    asm volatile("mma.sync.aligned.m16n8k16.row.col.f32.bf16.bf16.f32 "
        "{%0,%1,%2,%3},{%4,%5,%6,%7},{%8,%9},{%0,%1,%2,%3};"
        : "+f"(d[0]),"+f"(d[1]),"+f"(d[2]),"+f"(d[3])
        : "r"(a[0]),"r"(a[1]),"r"(a[2]),"r"(a[3]),"r"(b0),"r"(b1));
}
static __device__ __forceinline__ void split2(float f0, float f1, uint32_t& hi, uint32_t& lo){
    __nv_bfloat162 h = __floats2bfloat162_rn(f0, f1);
    __nv_bfloat162 l = __floats2bfloat162_rn(f0-__bfloat162float(h.x), f1-__bfloat162float(h.y));
    hi = *reinterpret_cast<uint32_t*>(&h); lo = *reinterpret_cast<uint32_t*>(&l);
}
static __device__ __forceinline__ float gelu_exact(float v){
    return 0.5f*v*(1.0f+erff(v*0.70710678118654752f));
}
// split 16 floats (4x float4) into hi/lo u32[8] each, store as 2+2 uint4
static __device__ __forceinline__ void split_store(const float4* r, uint32_t addr_hi, uint32_t addr_lo){
    uint32_t hi[8], lo[8];
#pragma unroll
    for (int p=0;p<4;p++){
        split2(r[p].x, r[p].y, hi[2*p],   lo[2*p]);
        split2(r[p].z, r[p].w, hi[2*p+1], lo[2*p+1]);
    }
    sts128(addr_hi,    hi[0],hi[1],hi[2],hi[3]);
    sts128(addr_hi+16, hi[4],hi[5],hi[6],hi[7]);
    sts128(addr_lo,    lo[0],lo[1],lo[2],lo[3]);
    sts128(addr_lo+16, lo[4],lo[5],lo[6],lo[7]);
}

__global__ void k_init(){
    int i = blockIdx.x*blockDim.x + threadIdx.x;
    if (i < NTP) g_perm[i] = -1;
    if (i < NE) { g_counts[i]=0; g_fill[i]=0; }
}
__global__ void k_count(const int* __restrict__ eid){
    int t = blockIdx.x*blockDim.x + threadIdx.x;
    if (t < NT) atomicAdd(&g_counts[eid[t]], 1);
}
__global__ void k_build(){
    int off=0, nt=0;
    for (int e=0;e<NE;e++){
        g_offsets[e]=off; int c=g_counts[e];
        for (int r=0;r<c;r+=BM){ g_tile_e[nt]=e; g_tile_row0[nt]=off+r; nt++; }
        off += (c + BM-1) & ~(BM-1);
    }
    g_offsets[NE]=off; g_ntiles=nt;
}
__global__ void k_scatter(const int* __restrict__ eid){
    int t = blockIdx.x*blockDim.x + threadIdx.x;
    if (t < NT){ int e=eid[t]; g_perm[g_offsets[e]+atomicAdd(&g_fill[e],1)]=t; }
}

// one BK=32 stage: 2 k16 steps, warp tile 32x64, 3 bf16 products per tile
static __device__ __forceinline__ void compute_stage(uint32_t sb, uint32_t aoff, uint32_t boff,
                                                     float acc[2][8][4]){
#pragma unroll
    for (int kg=0; kg<2; kg++){
        uint32_t Ah[2][4], Al[2][4];
#pragma unroll
        for (int mt=0; mt<2; mt++){
            uint32_t a = sb + OFF_AH + aoff + mt*(16*A_STRIDE) + kg*32;
            ldsm4(Ah[mt], a);
            ldsm4(Al[mt], a + (OFF_AL-OFF_AH));
        }
        uint32_t Bh[4][4], Bl[4][4];
#pragma unroll
        for (int np=0; np<4; np++){
            uint32_t b = sb + OFF_BH + boff + kg*(16*B_STRIDE) + np*32;
            ldsm4t(Bh[np], b);
            ldsm4t(Bl[np], b + (OFF_BL-OFF_BH));
        }
#pragma unroll
        for (int mt=0; mt<2; mt++)
#pragma unroll
            for (int nt=0; nt<8; nt++){
                uint32_t bh0 = Bh[nt>>1][(nt&1)*2], bh1 = Bh[nt>>1][(nt&1)*2+1];
                uint32_t bl0 = Bl[nt>>1][(nt&1)*2], bl1 = Bl[nt>>1][(nt&1)*2+1];
                mma16(acc[mt][nt], Ah[mt], bh0, bh1);
                mma16(acc[mt][nt], Al[mt], bh0, bh1);
                mma16(acc[mt][nt], Ah[mt], bl0, bl1);
            }
    }
}

// ========================= GEMM1 =========================
__global__ void __launch_bounds__(THREADS)
gemm1(const float* __restrict__ x, const float* __restrict__ w1,
      const float* __restrict__ b1)
{
    int tile = blockIdx.y;
    if (tile >= g_ntiles) return;
    const int e = g_tile_e[tile], row0 = g_tile_row0[tile];
    const int n0 = blockIdx.x * BN;
    const float* W = w1 + (size_t)e*NH*NI;

    extern __shared__ char sm[];
    __shared__ int Ptok[BM];
    __shared__ float sbias[BN];

    const uint32_t sb0 = s2u(sm);
    const int tid = threadIdx.x, w = tid>>5, l = tid&31;
    const int wm = w>>1, wn = w&1, gi = l>>2, tg = l&3;
    const int ar = tid>>1, ah = tid&1;     // A: row, 16-elem half
    const int br = tid>>3, bq = tid&7;     // B: k-row, 16-elem chunk
    const uint32_t aoff = (uint32_t)((wm*32 + (l&15))*A_STRIDE + (l>>4)*16);
    const uint32_t boff = (uint32_t)((l&15)*B_STRIDE + (wn*64)*2 + (l>>4)*16);

    if (tid < BM) Ptok[tid] = g_perm[row0 + tid];
    if (tid < BN) sbias[tid] = b1[(size_t)e*NI + n0 + tid];
    __syncthreads();

    float acc[2][8][4];
#pragma unroll
    for (int i=0;i<2;i++)
#pragma unroll
        for (int j=0;j<8;j++)
#pragma unroll
            for (int q=0;q<4;q++) acc[i][j][q]=0.f;

    float4 ra[4], rb[4];
    const int atok = Ptok[ar];
    auto pref = [&](int k0){
        if (atok >= 0){
            const float4* p = (const float4*)(x + (size_t)atok*NH + k0 + ah*16);
#pragma unroll
            for (int j=0;j<4;j++) ra[j] = p[j];
        } else {
#pragma unroll
            for (int j=0;j<4;j++) ra[j] = make_float4(0,0,0,0);
        }
        const float4* q = (const float4*)(W + (size_t)(k0+br)*NI + n0 + bq*16);
#pragma unroll
        for (int j=0;j<4;j++) rb[j] = q[j];
    };
    auto sts = [&](int b){
        uint32_t sb = sb0 + b*STAGE;
        uint32_t aa = sb + OFF_AH + ar*A_STRIDE + ah*32;
        split_store(ra, aa, aa + (OFF_AL-OFF_AH));
        uint32_t ba = sb + OFF_BH + br*B_STRIDE + bq*32;
        split_store(rb, ba, ba + (OFF_BL-OFF_BH));
    };

    const int KT = NH/BK;   // 24
    pref(0);
    for (int kt=0; kt<KT; kt++){
        int b = kt&1;
        sts(b);
        __syncthreads();
        if (kt+1<KT) pref((kt+1)*BK);
        compute_stage(sb0 + b*STAGE, aoff, boff, acc);
        __syncthreads();
    }

    // epilogue: bias + gelu, split to bf16 hi/lo planes
#pragma unroll
    for (int mt=0; mt<2; mt++){
#pragma unroll
        for (int half=0; half<2; half++){
            int gr = row0 + wm*32 + mt*16 + gi + half*8;
            uint32_t* ph = (uint32_t*)(g_inter_hi + (size_t)gr*NI);
            uint32_t* pl = (uint32_t*)(g_inter_lo + (size_t)gr*NI);
#pragma unroll
            for (int nt=0; nt<8; nt++){
                int c = n0 + wn*64 + nt*8 + tg*2;
                float v0 = gelu_exact(acc[mt][nt][half*2]   + sbias[wn*64 + nt*8 + tg*2]);
                float v1 = gelu_exact(acc[mt][nt][half*2+1] + sbias[wn*64 + nt*8 + tg*2 + 1]);
                uint32_t hi, lo; split2(v0, v1, hi, lo);
                ph[c>>1] = hi; pl[c>>1] = lo;
            }
        }
    }
}

// ========================= GEMM2 =========================
__global__ void __launch_bounds__(THREADS)
gemm2(const float* __restrict__ x, const float* __restrict__ w2,
      const float* __restrict__ b2)
{
    int tile = blockIdx.y;
    if (tile >= g_ntiles) return;
    const int e = g_tile_e[tile], row0 = g_tile_row0[tile];
    const int n0 = blockIdx.x * BN;
    const float* W = w2 + (size_t)e*NI*NH;

    extern __shared__ char sm[];
    __shared__ int Ptok[BM];
    __shared__ float sbias[BN];

    const uint32_t sb0 = s2u(sm);
    const int tid = threadIdx.x, w = tid>>5, l = tid&31;
    const int wm = w>>1, wn = w&1, gi = l>>2, tg = l&3;
    const int ar = tid>>1, ah = tid&1;
    const int br = tid>>3, bq = tid&7;
    const uint32_t aoff = (uint32_t)((wm*32 + (l&15))*A_STRIDE + (l>>4)*16);
    const uint32_t boff = (uint32_t)((l&15)*B_STRIDE + (wn*64)*2 + (l>>4)*16);

    if (tid < BM) Ptok[tid] = g_perm[row0 + tid];
    if (tid < BN) sbias[tid] = b2[(size_t)e*NH + n0 + tid];
    __syncthreads();

    float acc[2][8][4];
#pragma unroll
    for (int i=0;i<2;i++)
#pragma unroll
        for (int j=0;j<8;j++)
#pragma unroll
            for (int q=0;q<4;q++) acc[i][j][q]=0.f;

    uint4 uah[2], ual[2]; float4 rb[4];
    auto pref = [&](int k0){
        size_t base = (size_t)(row0+ar)*NI + k0 + ah*16;
        const uint4* ph = (const uint4*)(g_inter_hi + base);
        const uint4* pl = (const uint4*)(g_inter_lo + base);
        uah[0] = ph[0]; uah[1] = ph[1];
        ual[0] = pl[0]; ual[1] = pl[1];
        const float4* q = (const float4*)(W + (size_t)(k0+br)*NH + n0 + bq*16);
#pragma unroll
        for (int j=0;j<4;j++) rb[j] = q[j];
    };
    auto sts = [&](int b){
        uint32_t sb = sb0 + b*STAGE;
        uint32_t aa = sb + OFF_AH + ar*A_STRIDE + ah*32;
        sts128(aa,    uah[0].x,uah[0].y,uah[0].z,uah[0].w);
        sts128(aa+16, uah[1].x,uah[1].y,uah[1].z,uah[1].w);
        uint32_t al = aa + (OFF_AL-OFF_AH);
        sts128(al,    ual[0].x,ual[0].y,ual[0].z,ual[0].w);
        sts128(al+16, ual[1].x,ual[1].y,ual[1].z,ual[1].w);
        uint32_t ba = sb + OFF_BH + br*B_STRIDE + bq*32;
        split_store(rb, ba, ba + (OFF_BL-OFF_BH));
    };

    const int KT = NI/BK;   // 96
    pref(0);
    for (int kt=0; kt<KT; kt++){
        int b = kt&1;
        sts(b);
        __syncthreads();
        if (kt+1<KT) pref((kt+1)*BK);
        compute_stage(sb0 + b*STAGE, aoff, boff, acc);
        __syncthreads();
    }

    // epilogue: +bias +residual, scatter to token order
#pragma unroll
    for (int mt=0; mt<2; mt++){
#pragma unroll
        for (int half=0; half<2; half++){
            int lr = wm*32 + mt*16 + gi + half*8;
            int tok = Ptok[lr];
            if (tok < 0) continue;
            float* orow = g_mid + (size_t)tok*NH + n0 + wn*64;
            const float* xr = x + (size_t)tok*NH + n0 + wn*64;
#pragma unroll
            for (int nt=0; nt<8; nt++){
                int c = nt*8 + tg*2;
                float2 r = *(const float2*)(xr + c);
                float2 o;
                o.x = acc[mt][nt][half*2]   + sbias[wn*64 + c]     + r.x;
                o.y = acc[mt][nt][half*2+1] + sbias[wn*64 + c + 1] + r.y;
                *(float2*)(orow + c) = o;
            }
        }
    }
}

// ========================= LayerNorm =========================
__global__ void ln_kernel(const float* __restrict__ gamma,
                          const float* __restrict__ beta,
                          float* __restrict__ out)
{
    const int t = blockIdx.x;
    const float* v = g_mid + (size_t)t*NH;
    float* o = out + (size_t)t*NH;
    float s=0.f, s2=0.f;
    for (int h=threadIdx.x; h<NH; h+=blockDim.x){ float a=v[h]; s+=a; s2+=a*a; }
#pragma unroll
    for (int off=16; off; off>>=1){
        s  += __shfl_down_sync(0xffffffffu, s, off);
        s2 += __shfl_down_sync(0xffffffffu, s2, off);
    }
    __shared__ float sh_s[8], sh_s2[8];
    int w = threadIdx.x>>5, l = threadIdx.x&31;
    if (l==0){ sh_s[w]=s; sh_s2[w]=s2; }
    __syncthreads();
    float S=0.f, S2=0.f;
#pragma unroll
    for (int i=0;i<8;i++){ S+=sh_s[i]; S2+=sh_s2[i]; }
    const float inv_h = 1.0f/(float)NH;
    float mean = S*inv_h;
    float var  = S2*inv_h - mean*mean;
    float rstd = rsqrtf(var + 1e-12f);
    for (int h=threadIdx.x; h<NH; h+=blockDim.x)
        o[h] = (v[h]-mean)*rstd*gamma[h] + beta[h];
}

extern "C" void kernel_launch(void* const* d_in, const int* in_sizes, int n_in,
                              void* d_out, int out_size)
{
    const float* x     = (const float*)d_in[0];
    const float* w1    = (const float*)d_in[1];
    const float* b1    = (const float*)d_in[2];
    const float* w2    = (const float*)d_in[3];
    const float* b2    = (const float*)d_in[4];
    const float* gamma = (const float*)d_in[5];
    const float* beta  = (const float*)d_in[6];
    const int*   eid   = (const int*)d_in[7];
    float* out = (float*)d_out;

    static bool attr_set = false;
    if (!attr_set){
        cudaFuncSetAttribute(gemm1, cudaFuncAttributeMaxDynamicSharedMemorySize, SMEM_BYTES);
        cudaFuncSetAttribute(gemm2, cudaFuncAttributeMaxDynamicSharedMemorySize, SMEM_BYTES);
        attr_set = true;
    }

    k_init<<<(NTP+255)/256, 256>>>();
    k_count<<<NT/256, 256>>>(eid);
    k_build<<<1,1>>>();
    k_scatter<<<NT/256, 256>>>(eid);

    gemm1<<<dim3(NI/BN, MAX_TILES), THREADS, SMEM_BYTES>>>(x, w1, b1);
    gemm2<<<dim3(NH/BN, MAX_TILES), THREADS, SMEM_BYTES>>>(x, w2, b2);
    ln_kernel<<<NT, 256>>>(gamma, beta, out);
}

// round 7
// speedup vs baseline: 2.5914x; 2.5914x over previous
#include <cuda_runtime.h>
#include <math.h>
#include <stdint.h>

#define NE 8
#define NT 8192
#define NH 768
#define NI 3072
#define BM 128
#define BN 128
#define BK 32
#define THREADS 256
#define MAX_TILES 72
#define NTP (NT + NE*BM)

#define A_LD 36
#define B_LD 132
#define A_FLOATS (BM*A_LD)                 // 4608
#define STAGE_FLOATS (BM*A_LD + BK*B_LD)   // 8832
#define NSTAGE 3
#define SMEM_BYTES (NSTAGE*STAGE_FLOATS*4) // 105984

__device__ int g_counts[NE];
__device__ int g_fill[NE];
__device__ int g_offsets[NE+1];
__device__ int g_perm[NTP];
__device__ int g_tile_e[MAX_TILES];
__device__ int g_tile_row0[MAX_TILES];
__device__ int g_ntiles;
__device__ float g_inter[(size_t)NTP*NI];
__device__ float g_mid[(size_t)NT*NH];

static __device__ __forceinline__ void cp16(void* dst, const void* src, int sz){
    unsigned d = (unsigned)__cvta_generic_to_shared(dst);
    asm volatile("cp.async.cg.shared.global [%0], [%1], 16, %2;" :: "r"(d), "l"(src), "r"(sz) : "memory");
}
static __device__ __forceinline__ void cp_commit(){ asm volatile("cp.async.commit_group;" ::: "memory"); }
static __device__ __forceinline__ void cp_wait1(){ asm volatile("cp.async.wait_group 1;" ::: "memory"); }
static __device__ __forceinline__ void cp_wait0(){ asm volatile("cp.async.wait_group 0;" ::: "memory"); }

static __device__ __forceinline__ void mma8(float* d, uint32_t a0, uint32_t a1,
                                            uint32_t a2, uint32_t a3,
                                            uint32_t b0, uint32_t b1){
    asm volatile("mma.sync.aligned.m16n8k8.row.col.f32.tf32.tf32.f32 "
        "{%0,%1,%2,%3},{%4,%5,%6,%7},{%8,%9},{%0,%1,%2,%3};"
        : "+f"(d[0]),"+f"(d[1]),"+f"(d[2]),"+f"(d[3])
        : "r"(a0),"r"(a1),"r"(a2),"r"(a3),"r"(b0),"r"(b1));
}
static __device__ __forceinline__ float gelu_exact(float v){
    return 0.5f*v*(1.0f+erff(v*0.70710678118654752f));
}

__global__ void k_count(const int* __restrict__ eid){
    int t = blockIdx.x*blockDim.x + threadIdx.x;
    if (t < NT) atomicAdd(&g_counts[eid[t]], 1);
}
__global__ void k_build(){
    int off=0, nt=0;
    for (int e=0;e<NE;e++){
        g_offsets[e]=off; int c=g_counts[e];
        for (int r=0;r<c;r+=BM){ g_tile_e[nt]=e; g_tile_row0[nt]=off+r; nt++; }
        off += (c + BM-1) & ~(BM-1);
    }
    g_offsets[NE]=off; g_ntiles=nt;
}
__global__ void k_scatter(const int* __restrict__ eid){
    int t = blockIdx.x*blockDim.x + threadIdx.x;
    if (t < NT){ int e=eid[t]; g_perm[g_offsets[e]+atomicAdd(&g_fill[e],1)]=t; }
}

// one BK=32 stage: warp tile 32x64, raw-f32 operands (HW tf32 truncation)
static __device__ __forceinline__ void compute_stage(const float* As, const float* Bs,
                                                     int wm, int wn, int gi, int tg,
                                                     float acc[2][8][4]){
    const float* aptr = As + (wm*32 + gi)*A_LD + tg;
    const float* bptr = Bs + tg*B_LD + wn*64 + gi;
#pragma unroll
    for (int kk=0; kk<BK; kk+=8){
        uint32_t a[2][4];
#pragma unroll
        for (int mt=0; mt<2; mt++){
            const float* p = aptr + mt*16*A_LD + kk;
            a[mt][0] = __float_as_uint(p[0]);
            a[mt][1] = __float_as_uint(p[8*A_LD]);
            a[mt][2] = __float_as_uint(p[4]);
            a[mt][3] = __float_as_uint(p[8*A_LD+4]);
        }
        uint32_t b[8][2];
#pragma unroll
        for (int nt=0; nt<8; nt++){
            b[nt][0] = __float_as_uint(bptr[kk*B_LD + nt*8]);
            b[nt][1] = __float_as_uint(bptr[(kk+4)*B_LD + nt*8]);
        }
#pragma unroll
        for (int mt=0; mt<2; mt++)
#pragma unroll
            for (int nt=0; nt<8; nt++)
                mma8(acc[mt][nt], a[mt][0],a[mt][1],a[mt][2],a[mt][3], b[nt][0],b[nt][1]);
    }
}

// ========================= GEMM1 =========================
__global__ void __launch_bounds__(THREADS, 2)
gemm1(const float* __restrict__ x, const float* __restrict__ w1,
      const float* __restrict__ b1)
{
    int tile = blockIdx.y;
    if (tile >= g_ntiles) return;
    const int e = g_tile_e[tile], row0 = g_tile_row0[tile];
    const int n0 = blockIdx.x * BN;
    const float* W = w1 + (size_t)e*NH*NI;

    extern __shared__ float sm[];
    __shared__ float sbias[BN];

    const int tid = threadIdx.x, w = tid>>5, l = tid&31;
    const int wm = w>>1, wn = w&1, gi = l>>2, tg = l&3;

    if (tid < BN) sbias[tid] = b1[(size_t)e*NI + n0 + tid];

    // per-thread fixed gather rows for A chunks
    int rtok[4];
#pragma unroll
    for (int u=0;u<4;u++) rtok[u] = g_perm[row0 + ((tid + u*THREADS)>>3)];

    float acc[2][8][4];
#pragma unroll
    for (int i=0;i<2;i++)
#pragma unroll
        for (int j=0;j<8;j++)
#pragma unroll
            for (int q=0;q<4;q++) acc[i][j][q]=0.f;

    auto issue = [&](int kt){
        int buf = kt % NSTAGE;
        float* as = sm + buf*STAGE_FLOATS;
        float* bs = as + A_FLOATS;
        int k0 = kt*BK;
#pragma unroll
        for (int u=0;u<4;u++){
            int i = tid + u*THREADS;
            int r = i>>3, c4 = (i&7)*4;
            int tok = rtok[u];
            const float* src = (tok>=0) ? x + (size_t)tok*NH + k0 + c4 : x;
            cp16(as + r*A_LD + c4, src, (tok>=0)?16:0);
        }
#pragma unroll
        for (int u=0;u<4;u++){
            int i = tid + u*THREADS;
            int r = i>>5, c4 = (i&31)*4;
            cp16(bs + r*B_LD + c4, W + (size_t)(k0+r)*NI + n0 + c4, 16);
        }
        cp_commit();
    };

    const int KT = NH/BK;   // 24
    issue(0); issue(1);
    for (int kt=0; kt<KT; kt++){
        if (kt+1 < KT) cp_wait1(); else cp_wait0();
        __syncthreads();
        int buf = kt % NSTAGE;
        compute_stage(sm + buf*STAGE_FLOATS, sm + buf*STAGE_FLOATS + A_FLOATS,
                      wm, wn, gi, tg, acc);
        if (kt+2 < KT) issue(kt+2);
    }

    // epilogue: bias + gelu -> g_inter (sorted order, f32)
#pragma unroll
    for (int mt=0; mt<2; mt++){
#pragma unroll
        for (int half=0; half<2; half++){
            int gr = row0 + wm*32 + mt*16 + gi + half*8;
            float* orow = g_inter + (size_t)gr*NI + n0 + wn*64;
#pragma unroll
            for (int nt=0; nt<8; nt++){
                int c = nt*8 + tg*2;
                float v0 = acc[mt][nt][half*2]   + sbias[wn*64 + c];
                float v1 = acc[mt][nt][half*2+1] + sbias[wn*64 + c + 1];
                *(float2*)(orow + c) = make_float2(gelu_exact(v0), gelu_exact(v1));
            }
        }
    }
}

// ========================= GEMM2 =========================
__global__ void __launch_bounds__(THREADS, 2)
gemm2(const float* __restrict__ x, const float* __restrict__ w2,
      const float* __restrict__ b2)
{
    int tile = blockIdx.y;
    if (tile >= g_ntiles) return;
    const int e = g_tile_e[tile], row0 = g_tile_row0[tile];
    const int n0 = blockIdx.x * BN;
    const float* W = w2 + (size_t)e*NI*NH;

    extern __shared__ float sm[];
    __shared__ int Ptok[BM];
    __shared__ float sbias[BN];

    const int tid = threadIdx.x, w = tid>>5, l = tid&31;
    const int wm = w>>1, wn = w&1, gi = l>>2, tg = l&3;

    if (tid < BM) Ptok[tid] = g_perm[row0 + tid];
    if (tid < BN) sbias[tid] = b2[(size_t)e*NH + n0 + tid];

    float acc[2][8][4];
#pragma unroll
    for (int i=0;i<2;i++)
#pragma unroll
        for (int j=0;j<8;j++)
#pragma unroll
            for (int q=0;q<4;q++) acc[i][j][q]=0.f;

    auto issue = [&](int kt){
        int buf = kt % NSTAGE;
        float* as = sm + buf*STAGE_FLOATS;
        float* bs = as + A_FLOATS;
        int k0 = kt*BK;
#pragma unroll
        for (int u=0;u<4;u++){
            int i = tid + u*THREADS;
            int r = i>>3, c4 = (i&7)*4;
            cp16(as + r*A_LD + c4, g_inter + (size_t)(row0+r)*NI + k0 + c4, 16);
        }
#pragma unroll
        for (int u=0;u<4;u++){
            int i = tid + u*THREADS;
            int r = i>>5, c4 = (i&31)*4;
            cp16(bs + r*B_LD + c4, W + (size_t)(k0+r)*NH + n0 + c4, 16);
        }
        cp_commit();
    };

    const int KT = NI/BK;   // 96
    issue(0); issue(1);
    for (int kt=0; kt<KT; kt++){
        if (kt+1 < KT) cp_wait1(); else cp_wait0();
        __syncthreads();
        int buf = kt % NSTAGE;
        compute_stage(sm + buf*STAGE_FLOATS, sm + buf*STAGE_FLOATS + A_FLOATS,
                      wm, wn, gi, tg, acc);
        if (kt+2 < KT) issue(kt+2);
    }

    // epilogue: +bias +residual, scatter to token order
#pragma unroll
    for (int mt=0; mt<2; mt++){
#pragma unroll
        for (int half=0; half<2; half++){
            int lr = wm*32 + mt*16 + gi + half*8;
            int tok = Ptok[lr];
            if (tok < 0) continue;
            float* orow = g_mid + (size_t)tok*NH + n0 + wn*64;
            const float* xr = x + (size_t)tok*NH + n0 + wn*64;
#pragma unroll
            for (int nt=0; nt<8; nt++){
                int c = nt*8 + tg*2;
                float2 r = *(const float2*)(xr + c);
                float2 o;
                o.x = acc[mt][nt][half*2]   + sbias[wn*64 + c]     + r.x;
                o.y = acc[mt][nt][half*2+1] + sbias[wn*64 + c + 1] + r.y;
                *(float2*)(orow + c) = o;
            }
        }
    }
}

// ========================= LayerNorm =========================
__global__ void ln_kernel(const float* __restrict__ gamma,
                          const float* __restrict__ beta,
                          float* __restrict__ out)
{
    const int t = blockIdx.x;
    const float* v = g_mid + (size_t)t*NH;
    float* o = out + (size_t)t*NH;
    float s=0.f, s2=0.f;
    for (int h=threadIdx.x; h<NH; h+=blockDim.x){ float a=v[h]; s+=a; s2+=a*a; }
#pragma unroll
    for (int off=16; off; off>>=1){
        s  += __shfl_down_sync(0xffffffffu, s, off);
        s2 += __shfl_down_sync(0xffffffffu, s2, off);
    }
    __shared__ float sh_s[8], sh_s2[8];
    int w = threadIdx.x>>5, l = threadIdx.x&31;
    if (l==0){ sh_s[w]=s; sh_s2[w]=s2; }
    __syncthreads();
    float S=0.f, S2=0.f;
#pragma unroll
    for (int i=0;i<8;i++){ S+=sh_s[i]; S2+=sh_s2[i]; }
    const float inv_h = 1.0f/(float)NH;
    float mean = S*inv_h;
    float var  = S2*inv_h - mean*mean;
    float rstd = rsqrtf(var + 1e-12f);
    for (int h=threadIdx.x; h<NH; h+=blockDim.x)
        o[h] = (v[h]-mean)*rstd*gamma[h] + beta[h];
}

extern "C" void kernel_launch(void* const* d_in, const int* in_sizes, int n_in,
                              void* d_out, int out_size)
{
    const float* x     = (const float*)d_in[0];
    const float* w1    = (const float*)d_in[1];
    const float* b1    = (const float*)d_in[2];
    const float* w2    = (const float*)d_in[3];
    const float* b2    = (const float*)d_in[4];
    const float* gamma = (const float*)d_in[5];
    const float* beta  = (const float*)d_in[6];
    const int*   eid   = (const int*)d_in[7];
    float* out = (float*)d_out;

    static void *p_perm = nullptr, *p_counts = nullptr, *p_fill = nullptr;
    static bool init_done = false;
    if (!init_done){
        cudaFuncSetAttribute(gemm1, cudaFuncAttributeMaxDynamicSharedMemorySize, SMEM_BYTES);
        cudaFuncSetAttribute(gemm2, cudaFuncAttributeMaxDynamicSharedMemorySize, SMEM_BYTES);
        cudaGetSymbolAddress(&p_perm,   g_perm);
        cudaGetSymbolAddress(&p_counts, g_counts);
        cudaGetSymbolAddress(&p_fill,   g_fill);
        init_done = true;
    }

    cudaMemsetAsync(p_perm,   0xFF, NTP*sizeof(int));   // -1
    cudaMemsetAsync(p_counts, 0,    NE*sizeof(int));
    cudaMemsetAsync(p_fill,   0,    NE*sizeof(int));

    k_count<<<NT/256, 256>>>(eid);
    k_build<<<1,1>>>();
    k_scatter<<<NT/256, 256>>>(eid);

    gemm1<<<dim3(NI/BN, MAX_TILES), THREADS, SMEM_BYTES>>>(x, w1, b1);
    gemm2<<<dim3(NH/BN, MAX_TILES), THREADS, SMEM_BYTES>>>(x, w2, b2);
    ln_kernel<<<NT, 256>>>(gamma, beta, out);
}